// round 14
// baseline (speedup 1.0000x reference)
#include <cuda_runtime.h>
#include <math_constants.h>

// RoIPool: feature_map [B=2, H=50, W=50, C=256] f32, rpn_pred [B=2, N=128, 4] f32
// out [B, N, 7, 7, C] f32.
//   x1=(int)(W*p0); y1=(int)(H*p1); x2=(int)(W*p2); y2=(int)(H*p3)
//   sw=(x2-x1)/7; sh=(y2-y1)/7   (in [1,4] by input construction)
//   out[b,n,i,j,c] = max_{r<sh,t<sw} fm[b, y1+i*sh+r, x1+j*sw+t, c]
//
// R14 = R11 (pm22 range-max table, cuts gather traffic ~3x) + R12 (explicit
// register staging, cuts serialized L2 exposures). Decomposition makes every
// window <= 4 cells:
//   sh,sw>=2 : <=2x2 pm22 corner reads (s=2->{0}, s=3->{0,1}, s=4->{0,2})
//   any s==1 : direct fm reads along that dim (<=4 cells)
// Warp = ONE bin, thread = 8 channels (f4 {lane, lane+32}): whole window is
// ONE staged chunk of <=8 LDG.128 -> exactly one L2 exposure per thread.
// CTA = 224 thr = 7 bins; grid (7,128,2) exact. launch_bounds(224,5).

#define POOL 7
#define NROIS 128
#define BB 2
#define HH 50
#define WW 50
#define CC 256
#define C4 (CC / 4)   // 64 float4 per pixel
#define NBINS (POOL * POOL)       // 49
#define THREADS 224
#define ROWF4 (WW * C4)           // 3200 float4 per (b,y) row

__device__ float4 g_pm22[BB * HH * WW * C4];   // 5.12 MB scratch table

__device__ __forceinline__ void fmax4(float4& m, const float4 v) {
    m.x = fmaxf(m.x, v.x);
    m.y = fmaxf(m.y, v.y);
    m.z = fmaxf(m.z, v.z);
    m.w = fmaxf(m.w, v.w);
}

// ---------------- Kernel 1: 2x2 block max table ----------------
__global__ __launch_bounds__(THREADS) void pm22_kernel(
    const float4* __restrict__ fm)
{
    const int y  = blockIdx.y;                 // 0..49
    const int b  = blockIdx.z;                 // 0..1
    const int yp = min(y + 1, HH - 1);

    const float4* row0 = fm + (b * HH + y ) * ROWF4;
    const float4* row1 = fm + (b * HH + yp) * ROWF4;
    float4*       orow = g_pm22 + (b * HH + y) * ROWF4;

    // 3200 f4 per row, 2 chunks x 1600, THREADS=224 -> strided loop.
    for (int e = blockIdx.x * 1600 + threadIdx.x;
         e < blockIdx.x * 1600 + 1600 && e < ROWF4; e += THREADS) {
        const int x  = e >> 6;
        const int c  = e & 63;
        const int xp = min(x + 1, WW - 1);
        float4 a = __ldg(row0 + x  * C4 + c);
        fmax4(a,  __ldg(row0 + xp * C4 + c));
        fmax4(a,  __ldg(row1 + x  * C4 + c));
        fmax4(a,  __ldg(row1 + xp * C4 + c));
        orow[e] = a;
    }
}

// ---------------- Kernel 2: pooled max, single staged exposure ----------------

// Exact SHxSW window, <=4 cells, 2 f4 per cell per thread. ALL loads issued
// before any fmax.
template<int SH, int SW>
__device__ __forceinline__ void window8(const float4* __restrict__ fmbase,
                                        const float4* __restrict__ pmbase,
                                        float4& acc0, float4& acc1) {
    if constexpr (SH >= 2 && SW >= 2) {
        constexpr int NR = (SH == 2) ? 1 : 2;
        constexpr int NC = (SW == 2) ? 1 : 2;
        constexpr int DR = (SH == 4) ? 2 : 1;
        constexpr int DC = (SW == 4) ? 2 : 1;
        float4 b0[NR * NC], b1[NR * NC];
        #pragma unroll
        for (int r = 0; r < NR; ++r)
            #pragma unroll
            for (int c = 0; c < NC; ++c) {
                const float4* cp = pmbase + (r * DR * WW + c * DC) * C4;
                b0[r * NC + c] = __ldg(cp);
                b1[r * NC + c] = __ldg(cp + 32);
            }
        #pragma unroll
        for (int k = 0; k < NR * NC; ++k) {
            fmax4(acc0, b0[k]);
            fmax4(acc1, b1[k]);
        }
    } else {
        // At least one dim == 1: direct fm reads along the other dim.
        constexpr int N   = (SH == 1) ? SW : SH;
        constexpr int STR = (SH == 1) ? 1 : WW;   // in pixels
        float4 b0[N], b1[N];
        #pragma unroll
        for (int k = 0; k < N; ++k) {
            const float4* cp = fmbase + k * STR * C4;
            b0[k] = __ldg(cp);
            b1[k] = __ldg(cp + 32);
        }
        #pragma unroll
        for (int k = 0; k < N; ++k) {
            fmax4(acc0, b0[k]);
            fmax4(acc1, b1[k]);
        }
    }
}

__global__ __launch_bounds__(THREADS, 5) void roi_pool_kernel(
    const float4* __restrict__ fm,     // [B*H*W*C4] float4
    const float4* __restrict__ rois,   // [B*N] float4 (x1,y1,x2,y2)
    float4*       __restrict__ out)    // [B*N*49*C4] float4
{
    const int warp = threadIdx.x >> 5;          // 0..6
    const int lane = threadIdx.x & 31;

    const int bin = blockIdx.x * POOL + warp;   // 0..48 exact
    const int n   = blockIdx.y;
    const int b   = blockIdx.z;

    const float4 rp = __ldg(rois + b * NROIS + n);
    const int x1 = (int)(WW * rp.x);
    const int y1 = (int)(HH * rp.y);
    const int sw = ((int)(WW * rp.z) - x1) / POOL;   // in [1,4]
    const int sh = ((int)(HH * rp.w) - y1) / POOL;   // in [1,4]

    const int i = bin / POOL;
    const int j = bin - i * POOL;

    const int cellOff =
        ((b * HH + (y1 + i * sh)) * WW + (x1 + j * sw)) * C4 + lane;
    const float4* fmbase = fm + cellOff;
    const float4* pmbase = g_pm22 + cellOff;

    const float NEG = -CUDART_INF_F;
    float4 acc0 = make_float4(NEG, NEG, NEG, NEG);
    float4 acc1 = make_float4(NEG, NEG, NEG, NEG);

    // CTA-uniform 16-way dispatch on (sh,sw).
    const int code = (sh - 1) * 4 + (sw - 1);
    switch (code) {
        case  0: window8<1,1>(fmbase, pmbase, acc0, acc1); break;
        case  1: window8<1,2>(fmbase, pmbase, acc0, acc1); break;
        case  2: window8<1,3>(fmbase, pmbase, acc0, acc1); break;
        case  3: window8<1,4>(fmbase, pmbase, acc0, acc1); break;
        case  4: window8<2,1>(fmbase, pmbase, acc0, acc1); break;
        case  5: window8<2,2>(fmbase, pmbase, acc0, acc1); break;
        case  6: window8<2,3>(fmbase, pmbase, acc0, acc1); break;
        case  7: window8<2,4>(fmbase, pmbase, acc0, acc1); break;
        case  8: window8<3,1>(fmbase, pmbase, acc0, acc1); break;
        case  9: window8<3,2>(fmbase, pmbase, acc0, acc1); break;
        case 10: window8<3,3>(fmbase, pmbase, acc0, acc1); break;
        case 11: window8<3,4>(fmbase, pmbase, acc0, acc1); break;
        case 12: window8<4,1>(fmbase, pmbase, acc0, acc1); break;
        case 13: window8<4,2>(fmbase, pmbase, acc0, acc1); break;
        case 14: window8<4,3>(fmbase, pmbase, acc0, acc1); break;
        default: window8<4,4>(fmbase, pmbase, acc0, acc1); break;
    }

    float4* obase = out + ((b * NROIS + n) * NBINS + bin) * C4 + lane;
    obase[0]  = acc0;
    obase[32] = acc1;
}

extern "C" void kernel_launch(void* const* d_in, const int* in_sizes, int n_in,
                              void* d_out, int out_size) {
    const float4* fm   = (const float4*)d_in[0];  // feature_map
    const float4* rois = (const float4*)d_in[1];  // rpn_pred as float4
    float4*       out  = (float4*)d_out;

    dim3 g1(2, HH, BB);                           // 200 CTAs
    pm22_kernel<<<g1, THREADS>>>(fm);

    dim3 g2(POOL, NROIS, BB);                     // 7 x 128 x 2 = 1792 CTAs
    roi_pool_kernel<<<g2, THREADS>>>(fm, rois, out);
}

// round 15
// speedup vs baseline: 1.1946x; 1.1946x over previous
#include <cuda_runtime.h>
#include <math_constants.h>

// RoIPool: feature_map [B=2, H=50, W=50, C=256] f32, rpn_pred [B=2, N=128, 4] f32
// out [B, N, 7, 7, C] f32.
//   x1=(int)(W*p0); y1=(int)(H*p1); x2=(int)(W*p2); y2=(int)(H*p3)
//   sw=(x2-x1)/7; sh=(y2-y1)/7   (in [1,4] by input construction)
//   out[b,n,i,j,c] = max_{r<sh,t<sw} fm[b, y1+i*sh+r, x1+j*sw+t, c]
// Bounds: x1+7*sw-1 <= x2-1 <= 49 (same for y) -> reference clip is dead code.
//
// R15 = R12 (single kernel; warp = ONE bin; thread = 8 channels; window cells
// staged in chunks of 4 with all 8 LDG.128 issued before any fmax) with the
// residency raised from 4 to 5 CTAs/SM via __launch_bounds__(224,5) (reg cap
// 56). Register pressure trimmed: one base pointer, 32-bit immediate offsets.
// CTA = 224 threads = 7 bins; grid (7,128,2) covers all 49 bins exactly.

#define POOL 7
#define NROIS 128
#define BB 2
#define HH 50
#define WW 50
#define CC 256
#define C4 (CC / 4)   // 64 float4 per pixel
#define NBINS (POOL * POOL)       // 49
#define THREADS 224               // 7 warps = 7 bins

__device__ __forceinline__ void fmax4(float4& m, const float4 v) {
    m.x = fmaxf(m.x, v.x);
    m.y = fmaxf(m.y, v.y);
    m.z = fmaxf(m.z, v.z);
    m.w = fmaxf(m.w, v.w);
}

// Exact SHxSW window, 2 float4 per cell per thread, chunks of 4 cells:
// all 8 loads of a chunk issued before any consumption. Offsets are
// compile-time immediates off a single base pointer.
template<int SH, int SW>
__device__ __forceinline__ void window8(const float4* __restrict__ base,
                                        float4& acc0, float4& acc1) {
    constexpr int NCELL = SH * SW;
    constexpr int NCHUNK = (NCELL + 3) / 4;
    #pragma unroll
    for (int g = 0; g < NCHUNK; ++g) {
        float4 buf0[4], buf1[4];
        // Issue phase: up to 8 independent LDG.128.
        #pragma unroll
        for (int u = 0; u < 4; ++u) {
            const int k = g * 4 + u;
            if (k < NCELL) {
                const int r = k / SW;
                const int t = k - r * SW;
                const int off = (r * WW + t) * C4;   // compile-time immediate
                buf0[u] = __ldg(base + off);
                buf1[u] = __ldg(base + off + 32);
            }
        }
        // Consume phase.
        #pragma unroll
        for (int u = 0; u < 4; ++u) {
            const int k = g * 4 + u;
            if (k < NCELL) {
                fmax4(acc0, buf0[u]);
                fmax4(acc1, buf1[u]);
            }
        }
    }
}

__global__ __launch_bounds__(THREADS, 5) void roi_pool_kernel(
    const float4* __restrict__ fm,     // [B*H*W*C4] float4
    const float4* __restrict__ rois,   // [B*N] float4 (x1,y1,x2,y2)
    float4*       __restrict__ out)    // [B*N*49*C4] float4
{
    const int warp = threadIdx.x >> 5;          // 0..6
    const int lane = threadIdx.x & 31;          // f4 index base

    const int bin = blockIdx.x * POOL + warp;   // 0..48 exact
    const int n   = blockIdx.y;
    const int b   = blockIdx.z;

    const float4 rp = __ldg(rois + b * NROIS + n);
    const int x1 = (int)(WW * rp.x);
    const int y1 = (int)(HH * rp.y);
    const int sw = ((int)(WW * rp.z) - x1) / POOL;   // in [1,4]
    const int sh = ((int)(HH * rp.w) - y1) / POOL;   // in [1,4]

    const int i = bin / POOL;
    const int j = bin - i * POOL;

    // Thread covers float4 indices {lane, lane+32} of each pixel.
    const float4* base =
        fm + ((b * HH + (y1 + i * sh)) * WW + (x1 + j * sw)) * C4 + lane;

    const float NEG = -CUDART_INF_F;
    float4 acc0 = make_float4(NEG, NEG, NEG, NEG);
    float4 acc1 = make_float4(NEG, NEG, NEG, NEG);

    // CTA-uniform 16-way dispatch on (sh,sw).
    const int code = (sh - 1) * 4 + (sw - 1);
    switch (code) {
        case  0: window8<1,1>(base, acc0, acc1); break;
        case  1: window8<1,2>(base, acc0, acc1); break;
        case  2: window8<1,3>(base, acc0, acc1); break;
        case  3: window8<1,4>(base, acc0, acc1); break;
        case  4: window8<2,1>(base, acc0, acc1); break;
        case  5: window8<2,2>(base, acc0, acc1); break;
        case  6: window8<2,3>(base, acc0, acc1); break;
        case  7: window8<2,4>(base, acc0, acc1); break;
        case  8: window8<3,1>(base, acc0, acc1); break;
        case  9: window8<3,2>(base, acc0, acc1); break;
        case 10: window8<3,3>(base, acc0, acc1); break;
        case 11: window8<3,4>(base, acc0, acc1); break;
        case 12: window8<4,1>(base, acc0, acc1); break;
        case 13: window8<4,2>(base, acc0, acc1); break;
        case 14: window8<4,3>(base, acc0, acc1); break;
        default: window8<4,4>(base, acc0, acc1); break;
    }

    float4* obase = out + ((b * NROIS + n) * NBINS + bin) * C4 + lane;
    obase[0]  = acc0;
    obase[32] = acc1;
}

extern "C" void kernel_launch(void* const* d_in, const int* in_sizes, int n_in,
                              void* d_out, int out_size) {
    const float4* fm   = (const float4*)d_in[0];  // feature_map
    const float4* rois = (const float4*)d_in[1];  // rpn_pred as float4
    float4*       out  = (float4*)d_out;

    dim3 grid(POOL, NROIS, BB);                   // 7 x 128 x 2 = 1792 CTAs
    roi_pool_kernel<<<grid, THREADS>>>(fm, rois, out);
}